// round 5
// baseline (speedup 1.0000x reference)
#include <cuda_runtime.h>
#include <cuda_bf16.h>
#include <math.h>

#define B 16
#define C 64
#define H 256
#define W 256
#define HW (H*W)            // 65536
#define WT 8                // w-tile per CTA
#define HC 8                // h-chunk size
#define PAD (WT + 1)        // 9: stride-9 smem, conflict-free transpose

// One CTA = (b, 8-wide w tile), 256 threads = 32 channel-slots x 8 w.
// Streams h in chunks of 8 with register double-buffering; x is read from DRAM
// exactly once and kept in registers for both the norm and the weighted sum.
// Softmax without max-subtraction (exp args bounded ~14 for N(0,1); the shift
// cancels algebraically in weighted_sum/weight_sum).
__global__ __launch_bounds__(256, 5) void fused_kernel(const float* __restrict__ x,
                                                       float* __restrict__ out) {
    __shared__ float part[HC * 32 * PAD];  // [k][slot][wl]  (9.2 KB)
    __shared__ float ew[HC * WT];          // exp weights per (k, w)
    __shared__ float comp[C * WT];         // compressed[c][w] (2 KB)

    const int b    = blockIdx.y;
    const int w0   = blockIdx.x * WT;
    const int tid  = threadIdx.x;
    const int lane = tid & 31;
    const int wy   = tid >> 5;             // warp 0..7
    const int wl   = lane & 7;             // local w 0..7
    const int slot = (wy << 2) + (lane >> 3);  // channel slot 0..31

    // thread owns channels c0 = slot, c1 = slot+32 at w = w0+wl
    const float* xb = x + (size_t)b * C * HW + w0 + wl;
    const float* x0 = xb + ((size_t)slot << 16);
    const float* x1 = xb + ((size_t)(slot + 32) << 16);

    float acc0 = 0.f, acc1 = 0.f;
    float Ssum = 0.f;   // per-thread running sum of exp weights for w = wl
                        // (identical across slots; the true softmax denominator)

    float v0[2][HC], v1[2][HC];
#pragma unroll
    for (int k = 0; k < HC; k++) { v0[0][k] = x0[k * W]; v1[0][k] = x1[k * W]; }

#pragma unroll 2
    for (int hc = 0; hc < H; hc += HC) {
        const int cur = (hc >> 3) & 1, nxt = cur ^ 1;

        // ---- partial squared norms into smem
#pragma unroll
        for (int k = 0; k < HC; k++)
            part[k * (32 * PAD) + slot * PAD + wl] =
                fmaf(v0[cur][k], v0[cur][k], v1[cur][k] * v1[cur][k]);

        // ---- prefetch next chunk (LDGs in flight across both barriers)
        if (hc + HC < H) {
#pragma unroll
            for (int k = 0; k < HC; k++) {
                v0[nxt][k] = x0[(hc + HC + k) * W];
                v1[nxt][k] = x1[(hc + HC + k) * W];
            }
        }
        __syncthreads();

        // ---- warp wy reduces h-slot k=wy for all 8 w's: norm -> exp
        {
            const int k = wy;
#pragma unroll
            for (int w = 0; w < WT; w++) {
                float s = part[k * (32 * PAD) + lane * PAD + w];  // stride 9: conflict-free
#pragma unroll
                for (int o = 16; o; o >>= 1) s += __shfl_xor_sync(0xffffffffu, s, o);
                float e = __expf(sqrtf(s));
                if (lane == 0) ew[k * WT + w] = e;
            }
        }
        __syncthreads();

        // ---- weighted accumulation from register-cached x
#pragma unroll
        for (int k = 0; k < HC; k++) {
            float e = ew[k * WT + wl];   // 8 addrs, 4-way multicast, conflict-free
            acc0 = fmaf(v0[cur][k], e, acc0);
            acc1 = fmaf(v1[cur][k], e, acc1);
            Ssum += e;
        }
    }

    const float sc = 1.0f / (Ssum * (1.0f + 1e-8f));
    comp[slot * WT + wl]        = acc0 * sc;
    comp[(slot + 32) * WT + wl] = acc1 * sc;
    __syncthreads();

    // ---- broadcast-write over h: float4 stores (32B per (c,h) row pair)
    const float4* comp4 = (const float4*)comp;   // [C][2] float4
    float* ob = out + (size_t)b * C * HW + w0;
    for (int i = tid; i < C * H * 2; i += 256) {
        int w4 = i & 1;
        int h  = (i >> 1) & 255;
        int c  = i >> 9;
        *(float4*)(ob + (size_t)(c << 16) + (h << 8) + (w4 << 2)) = comp4[c * 2 + w4];
    }
}

extern "C" void kernel_launch(void* const* d_in, const int* in_sizes, int n_in,
                              void* d_out, int out_size) {
    const float* x = (const float*)d_in[0];
    float* out = (float*)d_out;
    dim3 grid(W / WT, B);
    fused_kernel<<<grid, 256>>>(x, out);
}

// round 6
// speedup vs baseline: 1.3030x; 1.3030x over previous
#include <cuda_runtime.h>
#include <cuda_bf16.h>
#include <math.h>

#define B 16
#define C 64
#define H 256
#define W 256
#define HW (H*W)            // 65536
#define WT 16               // w-tile per CTA
#define HC 8                // h-chunk
#define NCH (H/HC)          // 32 chunks
#define PSTRIDE 17          // padded slot stride (odd -> conflict-free transpose)

// One CTA = (b, 16-wide w tile), 512 threads = 32 channel-slots x 16 w.
// x is read from DRAM exactly once, register-resident for norm AND weighted sum.
// ONE barrier per chunk via ping-pong pipelining:
//   iter i: STS part(i+1) ; BAR ; consume(i) ; load v(i+2) ; reduce(i+1)
// Softmax without max-subtraction (args bounded ~14 for N(0,1); shift cancels).
__global__ __launch_bounds__(512, 2) void fused_kernel(const float* __restrict__ x,
                                                       float* __restrict__ out) {
    __shared__ float part[2][HC * 32 * PSTRIDE];  // ping-pong partial sq-norms (~35 KB)
    __shared__ float ew[2][HC * WT];              // ping-pong exp weights
    __shared__ float comp[C * WT];                // compressed[c][w] (4 KB)

    const int b    = blockIdx.y;
    const int w0   = blockIdx.x * WT;
    const int tid  = threadIdx.x;
    const int lane = tid & 31;
    const int wy   = tid >> 5;           // warp 0..15 (also: w-column this warp reduces)
    const int wl   = lane & 15;          // local w
    const int slot = wy * 2 + (lane >> 4);   // channel slot 0..31

    const float* xb = x + (size_t)b * C * HW + w0 + wl;
    const float* x0 = xb + ((size_t)slot << 16);          // channel slot
    const float* x1 = xb + ((size_t)(slot + 32) << 16);   // channel slot+32

    float v0[2][HC], v1[2][HC];
    float acc0 = 0.f, acc1 = 0.f, Ssum = 0.f;

    // ---- prologue: load chunks 0 and 1; square chunk 0; reduce chunk 0
#pragma unroll
    for (int k = 0; k < HC; k++) {
        v0[0][k] = __ldcs(&x0[k * W]);
        v1[0][k] = __ldcs(&x1[k * W]);
    }
#pragma unroll
    for (int k = 0; k < HC; k++) {
        v0[1][k] = __ldcs(&x0[(HC + k) * W]);
        v1[1][k] = __ldcs(&x1[(HC + k) * W]);
    }
#pragma unroll
    for (int k = 0; k < HC; k++)
        part[0][k * (32 * PSTRIDE) + slot * PSTRIDE + wl] =
            fmaf(v0[0][k], v0[0][k], v1[0][k] * v1[0][k]);
    __syncthreads();
    // reduce(0): warp wy reduces w-column wy across 32 slots
#pragma unroll
    for (int k = 0; k < HC; k++) {
        float s = part[0][k * (32 * PSTRIDE) + lane * PSTRIDE + wy];
#pragma unroll
        for (int o = 16; o; o >>= 1) s += __shfl_xor_sync(0xffffffffu, s, o);
        if (lane == 0) ew[0][k * WT + wy] = __expf(sqrtf(s));
    }

    // ---- mainloop: ONE barrier per chunk
#pragma unroll 2
    for (int i = 0; i < NCH; i++) {
        const int cb = i & 1, nb = cb ^ 1;

        // square v(i+1) -> part[nb]   (v(i+1) loaded >=1 full phase ago)
        if (i + 1 < NCH) {
#pragma unroll
            for (int k = 0; k < HC; k++)
                part[nb][k * (32 * PSTRIDE) + slot * PSTRIDE + wl] =
                    fmaf(v0[nb][k], v0[nb][k], v1[nb][k] * v1[nb][k]);
        }

        __syncthreads();   // ew(i) visible; part(i+1) visible

        // consume(i): weighted accumulation from register-cached x
#pragma unroll
        for (int k = 0; k < HC; k++) {
            float e = ew[cb][k * WT + wl];
            acc0 = fmaf(v0[cb][k], e, acc0);
            acc1 = fmaf(v1[cb][k], e, acc1);
            Ssum += e;     // per-thread softmax denominator (uniform per wl)
        }

        // load v(i+2) into the buffer consume(i) just freed
        if (i + 2 < NCH) {
            const int hb = (i + 2) * HC;
#pragma unroll
            for (int k = 0; k < HC; k++) {
                v0[cb][k] = __ldcs(&x0[(hb + k) * W]);
                v1[cb][k] = __ldcs(&x1[(hb + k) * W]);
            }
        }

        // reduce(i+1): part[nb] -> ew[nb]
        if (i + 1 < NCH) {
#pragma unroll
            for (int k = 0; k < HC; k++) {
                float s = part[nb][k * (32 * PSTRIDE) + lane * PSTRIDE + wy];
#pragma unroll
                for (int o = 16; o; o >>= 1) s += __shfl_xor_sync(0xffffffffu, s, o);
                if (lane == 0) ew[nb][k * WT + wy] = __expf(sqrtf(s));
            }
        }
    }

    // ---- epilogue: normalize, stage compressed, broadcast-write
    const float sc = 1.0f / (Ssum * (1.0f + 1e-8f));
    comp[slot * WT + wl]        = acc0 * sc;
    comp[(slot + 32) * WT + wl] = acc1 * sc;
    __syncthreads();

    const float4* comp4 = (const float4*)comp;   // [C][4] float4
    const int w4 = tid & 3;          // which float4 of the 16-w row
    const int hh = tid >> 2;         // h 0..127 (and hh+128)
    float* ob = out + (size_t)b * C * HW + w0 + (hh << 8) + (w4 << 2);
#pragma unroll 4
    for (int c = 0; c < C; c++) {
        float4 val = comp4[c * 4 + w4];
        __stcs((float4*)(ob + ((size_t)c << 16)), val);
        __stcs((float4*)(ob + ((size_t)c << 16) + (128 << 8)), val);
    }
}

extern "C" void kernel_launch(void* const* d_in, const int* in_sizes, int n_in,
                              void* d_out, int out_size) {
    const float* x = (const float*)d_in[0];
    float* out = (float*)d_out;
    dim3 grid(W / WT, B);
    fused_kernel<<<grid, 512>>>(x, out);
}

// round 7
// speedup vs baseline: 1.6814x; 1.2905x over previous
#include <cuda_runtime.h>
#include <cuda_bf16.h>
#include <math.h>

#define B 16
#define C 64
#define H 256
#define W 256
#define HW (H*W)        // 65536
#define WG 16           // w per CTA
#define NW 8            // warps per CTA
#define HPW (H/NW)      // 32 h per warp

// CTA = (b, 16-w tile), 256 threads = 8 warps. Warp wp streams h in
// [wp*32, wp*32+32) completely independently (ZERO barriers in mainloop):
//   lane = c3*4 + wq : loads float4 (4 w's) for channels c = c3 + 8j (j=0..7)
//   channel-L2 reduce = 3 in-warp shfl_xor over lane bits 2..4
//   e = exp(sqrt(.)) computed in-lane; acc[c][w] and sum(e) register-resident.
// One barrier total: combine 8 warp-partials via smem, then broadcast-write.
// Softmax without max-subtraction (args <= ~14 for N(0,1); shift cancels
// algebraically in weighted_sum/weight_sum).
__global__ __launch_bounds__(256) void fused_kernel(const float* __restrict__ x,
                                                    float* __restrict__ out) {
    __shared__ float4 red[NW][8][32];    // [warp][j][lane] acc partials (32 KB)
    __shared__ float4 ssred[NW][4];      // [warp][wq] sum-e partials
    __shared__ float4 comp_s[C][4];      // compressed[c][wq-float4] (4 KB)

    const int b    = blockIdx.y;
    const int w0   = blockIdx.x * WG;
    const int tid  = threadIdx.x;
    const int lane = tid & 31;
    const int wp   = tid >> 5;        // warp 0..7 -> h slice
    const int c3   = lane >> 2;       // 0..7 channel-group
    const int wq   = lane & 3;        // 0..3 float4-group of w

    const float* xb = x + (size_t)b * C * HW + w0 + wq * 4;

    float4 acc[8];
#pragma unroll
    for (int j = 0; j < 8; j++) acc[j] = make_float4(0.f, 0.f, 0.f, 0.f);
    float4 ssum = make_float4(0.f, 0.f, 0.f, 0.f);

    const int h0 = wp * HPW;
    for (int hi = 0; hi < HPW; hi++) {
        const float* ph = xb + (size_t)(h0 + hi) * W;
        float4 v[8];
#pragma unroll
        for (int j = 0; j < 8; j++)
            v[j] = __ldcs((const float4*)(ph + ((size_t)(c3 + 8 * j) << 16)));

        // partial squared norm over this lane's 8 channels (per w component)
        float4 sq = make_float4(0.f, 0.f, 0.f, 0.f);
#pragma unroll
        for (int j = 0; j < 8; j++) {
            sq.x = fmaf(v[j].x, v[j].x, sq.x);
            sq.y = fmaf(v[j].y, v[j].y, sq.y);
            sq.z = fmaf(v[j].z, v[j].z, sq.z);
            sq.w = fmaf(v[j].w, v[j].w, sq.w);
        }
        // reduce across c3 (lane bits 2..4): masks 4, 8, 16
#pragma unroll
        for (int m = 4; m <= 16; m <<= 1) {
            sq.x += __shfl_xor_sync(0xffffffffu, sq.x, m);
            sq.y += __shfl_xor_sync(0xffffffffu, sq.y, m);
            sq.z += __shfl_xor_sync(0xffffffffu, sq.z, m);
            sq.w += __shfl_xor_sync(0xffffffffu, sq.w, m);
        }
        float4 e;
        e.x = __expf(sqrtf(sq.x));
        e.y = __expf(sqrtf(sq.y));
        e.z = __expf(sqrtf(sq.z));
        e.w = __expf(sqrtf(sq.w));

#pragma unroll
        for (int j = 0; j < 8; j++) {
            acc[j].x = fmaf(v[j].x, e.x, acc[j].x);
            acc[j].y = fmaf(v[j].y, e.y, acc[j].y);
            acc[j].z = fmaf(v[j].z, e.z, acc[j].z);
            acc[j].w = fmaf(v[j].w, e.w, acc[j].w);
        }
        ssum.x += e.x; ssum.y += e.y; ssum.z += e.z; ssum.w += e.w;
    }

    // ---- dump warp partials (conflict-free: lane-consecutive float4)
#pragma unroll
    for (int j = 0; j < 8; j++) red[wp][j][lane] = acc[j];
    if (c3 == 0) ssred[wp][wq] = ssum;
    __syncthreads();

    // ---- combine: thread = (c = tid>>2, q = tid&3)
    {
        const int c = tid >> 2, q = tid & 3;
        float4 tot = make_float4(0.f, 0.f, 0.f, 0.f);
        float4 st  = make_float4(0.f, 0.f, 0.f, 0.f);
#pragma unroll
        for (int p = 0; p < NW; p++) {
            float4 a = red[p][c >> 3][(c & 7) * 4 + q];
            tot.x += a.x; tot.y += a.y; tot.z += a.z; tot.w += a.w;
            float4 s = ssred[p][q];
            st.x += s.x; st.y += s.y; st.z += s.z; st.w += s.w;
        }
        float4 o;
        o.x = tot.x / (st.x * (1.0f + 1e-8f));
        o.y = tot.y / (st.y * (1.0f + 1e-8f));
        o.z = tot.z / (st.z * (1.0f + 1e-8f));
        o.w = tot.w / (st.w * (1.0f + 1e-8f));
        comp_s[c][q] = o;
    }
    __syncthreads();

    // ---- broadcast-write over h: float4 stores, 64B contiguous per 4 lanes
    float* ob = out + (size_t)b * C * HW + w0;
    const int q  = tid & 3;
    const int hh = tid >> 2;          // 0..63
#pragma unroll 1
    for (int c = 0; c < C; c++) {
        float4 val = comp_s[c][q];
        float* oc = ob + ((size_t)c << 16) + q * 4;
#pragma unroll
        for (int hb = 0; hb < 4; hb++)
            __stcs((float4*)(oc + (size_t)(hb * 64 + hh) * W), val);
    }
}

extern "C" void kernel_launch(void* const* d_in, const int* in_sizes, int n_in,
                              void* d_out, int out_size) {
    const float* x = (const float*)d_in[0];
    float* out = (float*)d_out;
    dim3 grid(W / WG, B);
    fused_kernel<<<grid, 256>>>(x, out);
}